// round 4
// baseline (speedup 1.0000x reference)
#include <cuda_runtime.h>

#define S_TILE   16
#define KF       32
#define ROWS     48            // S_TILE + KF (ring buffer size)
#define CHAIN    4             // s-tiles per CTA
#define DCONST   1024
#define D4       256           // D / 4
#define PITCH4   257           // float4 pitch per row
#define COLS     48
#define NEG_BIG  -1.0e9f

#define TILE_F4      (ROWS * PITCH4)
#define RED_OFF      (TILE_F4 * 4)            // 49344
#define RED_SIZE     (8 * S_TILE * COLS)
#define W_OFF        (RED_OFF + RED_SIZE)     // 55488
#define SMEM_FLOATS  (W_OFF + S_TILE * COLS * 2)
#define SMEM_BYTES   (SMEM_FLOATS * 4)        // 228096 B

typedef unsigned long long u64;

__device__ __forceinline__ void fma2(u64& d, u64 a, u64 b) {
    asm("fma.rn.f32x2 %0, %1, %2, %0;" : "+l"(d) : "l"(a), "l"(b));
}
__device__ __forceinline__ float sum2(u64 a) {
    float2 v = *reinterpret_cast<float2*>(&a);
    return v.x + v.y;
}

__global__ __launch_bounds__(512, 1)
void future_encoder_kernel(const float* __restrict__ in,
                           float* __restrict__ out,
                           int S)
{
    extern __shared__ float smem[];
    ulonglong2* tileU = reinterpret_cast<ulonglong2*>(smem);
    float4*     tile4 = reinterpret_cast<float4*>(smem);
    float*      red   = smem + RED_OFF;
    u64*        Wd    = reinterpret_cast<u64*>(smem + W_OFF);
    float2*     Wd2   = reinterpret_cast<float2*>(smem + W_OFF);

    const int tid   = threadIdx.x;
    const int chain = blockIdx.x;
    const int bb    = blockIdx.y;
    const int t0    = chain * CHAIN;

    const float4* in4  = reinterpret_cast<const float4*>(in)  + (size_t)bb * S * D4;
    float4*       out4 = reinterpret_cast<float4*>(out)       + (size_t)bb * S * D4;

    // ---- initial load: 48 rows into slots 0..47 ----
    {
        const int half = tid >> 8;
        const int col  = tid & 255;
        #pragma unroll 4
        for (int it = 0; it < 24; ++it) {
            const int r = it * 2 + half;
            int gr = t0 * S_TILE + r;
            if (gr > S - 1) gr = S - 1;
            tile4[r * PITCH4 + col] = in4[(size_t)gr * D4 + col];
        }
    }

    int rot = 0;

    for (int tt = 0; tt < CHAIN; ++tt) {
        const int s0 = (t0 + tt) * S_TILE;
        __syncthreads();   // tile (loads / refresh) visible

        // ================= Phase A: broadcast-q scores =================
        // warp w = dim-group (16 float4 cols); lane owns f-rows j1=lane, j2=32+(lane&15)
        {
            const int w    = tid >> 5;
            const int lane = tid & 31;
            const int base = w * 16;

            int r1 = lane + rot;               if (r1 >= ROWS) r1 -= ROWS;
            int r2 = 32 + (lane & 15) + rot;   if (r2 >= ROWS) r2 -= ROWS;
            const int fs1 = r1 * PITCH4;
            const int fs2 = r2 * PITCH4;

            int qs[16];
            #pragma unroll
            for (int i = 0; i < 16; ++i) {
                int r = i + rot; if (r >= ROWS) r -= ROWS;
                qs[i] = r * PITCH4;
            }

            u64 acc1[16], acc2[16];
            #pragma unroll
            for (int i = 0; i < 16; ++i) { acc1[i] = 0ull; acc2[i] = 0ull; }

            #pragma unroll 4
            for (int step = 0; step < 16; ++step) {
                const int col = base + step;
                const ulonglong2 f1 = tileU[fs1 + col];   // strided, conflict-free
                const ulonglong2 f2 = tileU[fs2 + col];   // 16 distinct rows (dup half-warp)
                #pragma unroll
                for (int i = 0; i < 16; ++i) {
                    const ulonglong2 q = tileU[qs[i] + col];   // broadcast: 1 wavefront
                    fma2(acc1[i], q.x, f1.x);
                    fma2(acc1[i], q.y, f1.y);
                    fma2(acc2[i], q.x, f2.x);
                    fma2(acc2[i], q.y, f2.y);
                }
            }

            float* myred = red + (w & 7) * (S_TILE * COLS);
            if (w < 8) {
                #pragma unroll
                for (int i = 0; i < 16; ++i)
                    myred[i * COLS + lane] = sum2(acc1[i]);
                if (lane < 16) {
                    #pragma unroll
                    for (int i = 0; i < 16; ++i)
                        myred[i * COLS + 32 + lane] = sum2(acc2[i]);
                }
            }
            __syncthreads();   // wave-0 stores visible

            if (w >= 8) {
                #pragma unroll
                for (int i = 0; i < 16; ++i)
                    myred[i * COLS + lane] += sum2(acc1[i]);
                if (lane < 16) {
                    #pragma unroll
                    for (int i = 0; i < 16; ++i)
                        myred[i * COLS + 32 + lane] += sum2(acc2[i]);
                }
            }
        }

        // ---- early refresh LDG: next tile's 16 rows -> registers (latency hidden) ----
        float4 st[8];
        const bool do_refresh = (tt + 1 < CHAIN);
        if (do_refresh) {
            const int krow = tid >> 5;            // 0..15
            const int kcol = tid & 31;            // f4 col base
            int gr = s0 + ROWS + krow;
            if (gr > S - 1) gr = S - 1;
            const float4* src = in4 + (size_t)gr * D4 + kcol;
            #pragma unroll
            for (int c = 0; c < 8; ++c)
                st[c] = src[32 * c];
        }
        __syncthreads();   // red complete

        // ---- reduce mask softmax (warp = query row) ----
        {
            const int row  = tid >> 5;
            const int lane = tid & 31;

            float s1 = 0.0f, s2 = 0.0f;
            #pragma unroll
            for (int g = 0; g < 8; ++g)
                s1 += red[g * (S_TILE * COLS) + row * COLS + lane];
            if (lane < 16) {
                #pragma unroll
                for (int g = 0; g < 8; ++g)
                    s2 += red[g * (S_TILE * COLS) + row * COLS + 32 + lane];
            }

            const int j1 = lane;
            const int k1 = j1 - row - 1;
            const bool val1 = (k1 >= 0) && (k1 < KF) && (s0 + j1 < S);
            const float v1 = val1 ? s1 : NEG_BIG;

            const int j2 = 32 + lane;
            const int k2 = j2 - row - 1;
            const bool val2 = (lane < 16) && (k2 >= 0) && (k2 < KF) && (s0 + j2 < S);
            const float v2 = val2 ? s2 : NEG_BIG;

            float m = fmaxf(v1, v2);
            #pragma unroll
            for (int o = 16; o > 0; o >>= 1)
                m = fmaxf(m, __shfl_xor_sync(0xFFFFFFFFu, m, o));

            const float e1 = __expf(v1 - m);
            const float e2 = (lane < 16) ? __expf(v2 - m) : 0.0f;
            float sum = e1 + e2;
            #pragma unroll
            for (int o = 16; o > 0; o >>= 1)
                sum += __shfl_xor_sync(0xFFFFFFFFu, sum, o);
            const float inv = 1.0f / sum;

            const float w1 = val1 ? e1 * inv : 0.0f;
            Wd2[row * COLS + j1] = make_float2(w1, w1);
            if (lane < 16) {
                const float w2 = val2 ? e2 * inv : 0.0f;
                Wd2[row * COLS + j2] = make_float2(w2, w2);
            }
        }
        __syncthreads();   // weights ready

        // ================= Phase B: out = W * F =================
        {
            const int a = tid >> 8;     // rows a*8 .. a*8+7
            const int b = tid & 255;    // float4 column

            u64 acc[8][2];
            #pragma unroll
            for (int ii = 0; ii < 8; ++ii) { acc[ii][0] = 0ull; acc[ii][1] = 0ull; }

            #pragma unroll 2
            for (int jp = 0; jp < 24; ++jp) {
                const int jl = jp * 2;
                int sl1 = jl + rot;     if (sl1 >= ROWS) sl1 -= ROWS;
                int sl2 = jl + 1 + rot; if (sl2 >= ROWS) sl2 -= ROWS;
                const ulonglong2 f1 = tileU[sl1 * PITCH4 + b];
                const ulonglong2 f2 = tileU[sl2 * PITCH4 + b];
                #pragma unroll
                for (int ii = 0; ii < 8; ++ii) {
                    const ulonglong2 wp =
                        *reinterpret_cast<const ulonglong2*>(&Wd[(a * 8 + ii) * COLS + jl]);
                    fma2(acc[ii][0], wp.x, f1.x);
                    fma2(acc[ii][1], wp.x, f1.y);
                    fma2(acc[ii][0], wp.y, f2.x);
                    fma2(acc[ii][1], wp.y, f2.y);
                }
            }

            #pragma unroll
            for (int ii = 0; ii < 8; ++ii) {
                const int s = s0 + a * 8 + ii;
                if (s < S) {
                    const float2 lo = *reinterpret_cast<float2*>(&acc[ii][0]);
                    const float2 hi = *reinterpret_cast<float2*>(&acc[ii][1]);
                    out4[(size_t)s * D4 + b] = make_float4(lo.x, lo.y, hi.x, hi.y);
                }
            }
        }

        // ---- write stashed refresh rows into ring ----
        if (do_refresh) {
            __syncthreads();   // phase B reads done before overwrite
            const int krow = tid >> 5;
            const int kcol = tid & 31;
            int slot = rot + krow; if (slot >= ROWS) slot -= ROWS;
            float4* dst = tile4 + slot * PITCH4 + kcol;
            #pragma unroll
            for (int c = 0; c < 8; ++c)
                dst[32 * c] = st[c];
            rot += S_TILE; if (rot >= ROWS) rot -= ROWS;
        }
    }
}

extern "C" void kernel_launch(void* const* d_in, const int* in_sizes, int n_in,
                              void* d_out, int out_size)
{
    (void)n_in; (void)out_size;
    const float* in = (const float*)d_in[0];
    float* out = (float*)d_out;

    const int S = 2048;
    const int B = in_sizes[0] / (S * DCONST);
    const int chains = S / (S_TILE * CHAIN);   // 32

    cudaFuncSetAttribute(future_encoder_kernel,
                         cudaFuncAttributeMaxDynamicSharedMemorySize,
                         SMEM_BYTES);

    dim3 grid(chains, B);
    future_encoder_kernel<<<grid, 512, SMEM_BYTES>>>(in, out, S);
}

// round 5
// speedup vs baseline: 1.0694x; 1.0694x over previous
#include <cuda_runtime.h>

#define S_TILE   16
#define KF       32
#define ROWS     48            // S_TILE + KF (ring buffer size)
#define CHAIN    4             // s-tiles per CTA
#define DCONST   1024
#define D4       256           // D / 4
#define PITCH4   257           // float4 pitch per row
#define COLS     48
#define NEG_BIG  -1.0e9f

#define TILE_F4      (ROWS * PITCH4)
#define RED_OFF      (TILE_F4 * 4)            // 49344
#define RED_SIZE     (8 * S_TILE * COLS)
#define W_OFF        (RED_OFF + RED_SIZE)     // 55488
#define SMEM_FLOATS  (W_OFF + S_TILE * COLS * 2)
#define SMEM_BYTES   (SMEM_FLOATS * 4)        // 228096 B

typedef unsigned long long u64;

__device__ __forceinline__ void fma2(u64& d, u64 a, u64 b) {
    asm("fma.rn.f32x2 %0, %1, %2, %0;" : "+l"(d) : "l"(a), "l"(b));
}
__device__ __forceinline__ float sum2(u64 a) {
    float2 v = *reinterpret_cast<float2*>(&a);
    return v.x + v.y;
}

__global__ __launch_bounds__(512, 1)
void future_encoder_kernel(const float* __restrict__ in,
                           float* __restrict__ out,
                           int S)
{
    extern __shared__ float smem[];
    ulonglong2* tileU = reinterpret_cast<ulonglong2*>(smem);
    float4*     tile4 = reinterpret_cast<float4*>(smem);
    float*      red   = smem + RED_OFF;
    u64*        Wd    = reinterpret_cast<u64*>(smem + W_OFF);
    float2*     Wd2   = reinterpret_cast<float2*>(smem + W_OFF);

    const int tid   = threadIdx.x;
    const int chain = blockIdx.x;
    const int bb    = blockIdx.y;
    const int t0    = chain * CHAIN;

    const float4* in4  = reinterpret_cast<const float4*>(in)  + (size_t)bb * S * D4;
    float4*       out4 = reinterpret_cast<float4*>(out)       + (size_t)bb * S * D4;

    // ---- initial load: 48 rows into slots 0..47 ----
    {
        const int half = tid >> 8;
        const int col  = tid & 255;
        #pragma unroll 4
        for (int it = 0; it < 24; ++it) {
            const int r = it * 2 + half;
            int gr = t0 * S_TILE + r;
            if (gr > S - 1) gr = S - 1;
            tile4[r * PITCH4 + col] = in4[(size_t)gr * D4 + col];
        }
    }

    int rot = 0;

    for (int tt = 0; tt < CHAIN; ++tt) {
        const int s0 = (t0 + tt) * S_TILE;
        __syncthreads();   // tile (loads / refresh) visible

        // ===== Phase A: broadcast-q scores =====
        // warp = (d-group g: 32 f4 cols, i-half h). lane owns f-rows j1=lane, j2=32+(lane&15).
        // warp (g,h) writes red[g] rows [8h, 8h+8) -> disjoint, no extra barrier.
        {
            const int w    = tid >> 5;
            const int lane = tid & 31;
            const int g    = w >> 1;          // d-group 0..7
            const int h    = w & 1;           // i-half 0/1
            const int base = g * 32;          // f4 col start of this warp's 128-dim slice

            int r1 = lane + rot;               if (r1 >= ROWS) r1 -= ROWS;
            int r2 = 32 + (lane & 15) + rot;   if (r2 >= ROWS) r2 -= ROWS;
            const int fs1 = r1 * PITCH4;
            const int fs2 = r2 * PITCH4;

            int qs[8];
            #pragma unroll
            for (int i = 0; i < 8; ++i) {
                int r = 8 * h + i + rot; if (r >= ROWS) r -= ROWS;
                qs[i] = r * PITCH4;
            }

            u64 acc1[8], acc2[8];
            #pragma unroll
            for (int i = 0; i < 8; ++i) { acc1[i] = 0ull; acc2[i] = 0ull; }

            #pragma unroll 4
            for (int step = 0; step < 32; ++step) {
                const int col = base + step;
                const ulonglong2 f1 = tileU[fs1 + col];   // strided, conflict-free (4 wf)
                const ulonglong2 f2 = tileU[fs2 + col];   // half-dup rows (4 wf)
                #pragma unroll
                for (int i = 0; i < 8; ++i) {
                    const ulonglong2 q = tileU[qs[i] + col];   // broadcast (1 wf)
                    fma2(acc1[i], q.x, f1.x);
                    fma2(acc1[i], q.y, f1.y);
                    fma2(acc2[i], q.x, f2.x);
                    fma2(acc2[i], q.y, f2.y);
                }
            }

            float* myred = red + g * (S_TILE * COLS) + 8 * h * COLS;
            #pragma unroll
            for (int i = 0; i < 8; ++i)
                myred[i * COLS + lane] = sum2(acc1[i]);
            if (lane < 16) {
                #pragma unroll
                for (int i = 0; i < 8; ++i)
                    myred[i * COLS + 32 + lane] = sum2(acc2[i]);
            }
        }

        // ---- early refresh LDG: next tile's 16 rows -> registers ----
        float4 st[8];
        const bool do_refresh = (tt + 1 < CHAIN);
        if (do_refresh) {
            const int krow = tid >> 5;            // 0..15
            const int kcol = tid & 31;            // f4 col base
            int gr = s0 + ROWS + krow;
            if (gr > S - 1) gr = S - 1;
            const float4* src = in4 + (size_t)gr * D4 + kcol;
            #pragma unroll
            for (int c = 0; c < 8; ++c)
                st[c] = src[32 * c];
        }
        __syncthreads();   // red complete

        // ---- reduce over d-groups + mask + softmax (warp = query row) ----
        {
            const int row  = tid >> 5;
            const int lane = tid & 31;

            float s1 = 0.0f, s2 = 0.0f;
            #pragma unroll
            for (int g = 0; g < 8; ++g)
                s1 += red[g * (S_TILE * COLS) + row * COLS + lane];
            if (lane < 16) {
                #pragma unroll
                for (int g = 0; g < 8; ++g)
                    s2 += red[g * (S_TILE * COLS) + row * COLS + 32 + lane];
            }

            const int j1 = lane;
            const int k1 = j1 - row - 1;
            const bool val1 = (k1 >= 0) && (k1 < KF) && (s0 + j1 < S);
            const float v1 = val1 ? s1 : NEG_BIG;

            const int j2 = 32 + lane;
            const int k2 = j2 - row - 1;
            const bool val2 = (lane < 16) && (k2 >= 0) && (k2 < KF) && (s0 + j2 < S);
            const float v2 = val2 ? s2 : NEG_BIG;

            float m = fmaxf(v1, v2);
            #pragma unroll
            for (int o = 16; o > 0; o >>= 1)
                m = fmaxf(m, __shfl_xor_sync(0xFFFFFFFFu, m, o));

            const float e1 = __expf(v1 - m);
            const float e2 = (lane < 16) ? __expf(v2 - m) : 0.0f;
            float sum = e1 + e2;
            #pragma unroll
            for (int o = 16; o > 0; o >>= 1)
                sum += __shfl_xor_sync(0xFFFFFFFFu, sum, o);
            const float inv = 1.0f / sum;

            const float w1 = val1 ? e1 * inv : 0.0f;
            Wd2[row * COLS + j1] = make_float2(w1, w1);
            if (lane < 16) {
                const float w2 = val2 ? e2 * inv : 0.0f;
                Wd2[row * COLS + j2] = make_float2(w2, w2);
            }
        }
        __syncthreads();   // weights ready

        // ===== Phase B: out = W * F =====
        {
            const int a = tid >> 8;     // rows a*8 .. a*8+7
            const int b = tid & 255;    // float4 column

            u64 acc[8][2];
            #pragma unroll
            for (int ii = 0; ii < 8; ++ii) { acc[ii][0] = 0ull; acc[ii][1] = 0ull; }

            #pragma unroll 2
            for (int jp = 0; jp < 24; ++jp) {
                const int jl = jp * 2;
                int sl1 = jl + rot;     if (sl1 >= ROWS) sl1 -= ROWS;
                int sl2 = jl + 1 + rot; if (sl2 >= ROWS) sl2 -= ROWS;
                const ulonglong2 f1 = tileU[sl1 * PITCH4 + b];
                const ulonglong2 f2 = tileU[sl2 * PITCH4 + b];
                #pragma unroll
                for (int ii = 0; ii < 8; ++ii) {
                    const ulonglong2 wp =
                        *reinterpret_cast<const ulonglong2*>(&Wd[(a * 8 + ii) * COLS + jl]);
                    fma2(acc[ii][0], wp.x, f1.x);
                    fma2(acc[ii][1], wp.x, f1.y);
                    fma2(acc[ii][0], wp.y, f2.x);
                    fma2(acc[ii][1], wp.y, f2.y);
                }
            }

            #pragma unroll
            for (int ii = 0; ii < 8; ++ii) {
                const int s = s0 + a * 8 + ii;
                if (s < S) {
                    const float2 lo = *reinterpret_cast<float2*>(&acc[ii][0]);
                    const float2 hi = *reinterpret_cast<float2*>(&acc[ii][1]);
                    out4[(size_t)s * D4 + b] = make_float4(lo.x, lo.y, hi.x, hi.y);
                }
            }
        }

        // ---- write stashed refresh rows into ring ----
        if (do_refresh) {
            __syncthreads();   // phase B tile reads done before overwrite
            const int krow = tid >> 5;
            const int kcol = tid & 31;
            int slot = rot + krow; if (slot >= ROWS) slot -= ROWS;
            float4* dst = tile4 + slot * PITCH4 + kcol;
            #pragma unroll
            for (int c = 0; c < 8; ++c)
                dst[32 * c] = st[c];
            rot += S_TILE; if (rot >= ROWS) rot -= ROWS;
        }
    }
}

extern "C" void kernel_launch(void* const* d_in, const int* in_sizes, int n_in,
                              void* d_out, int out_size)
{
    (void)n_in; (void)out_size;
    const float* in = (const float*)d_in[0];
    float* out = (float*)d_out;

    const int S = 2048;
    const int B = in_sizes[0] / (S * DCONST);
    const int chains = S / (S_TILE * CHAIN);   // 32

    cudaFuncSetAttribute(future_encoder_kernel,
                         cudaFuncAttributeMaxDynamicSharedMemorySize,
                         SMEM_BYTES);

    dim3 grid(chains, B);
    future_encoder_kernel<<<grid, 512, SMEM_BYTES>>>(in, out, S);
}